// round 11
// baseline (speedup 1.0000x reference)
#include <cuda_runtime.h>
#include <cuda_bf16.h>
#include <mma.h>
#include <math.h>
#include <cstdint>

using namespace nvcuda;
typedef __nv_bfloat16 bf16;

#define SEQ   2048
#define DMOD  1024
#define NHEAD 16
#define HDIM  64
#define DMLP  8192

// ---------------- scratch -----------------------------------------------------
__device__ float g_xn  [SEQ * DMOD];
__device__ float g_qkv [SEQ * 3 * DMOD];
__device__ float g_attn[SEQ * DMOD];
__device__ float g_h   [SEQ * DMOD];
__device__ float g_hn  [SEQ * DMOD];
__device__ float g_g   [SEQ * DMLP];
__device__ float g_mlp [SEQ * (DMLP / 2)];
// head-major RoPE'd q/k/v, bf16 hi/lo:  [h][l][64]
__device__ bf16  g_qh[SEQ * DMOD], g_ql[SEQ * DMOD];
__device__ bf16  g_kh[SEQ * DMOD], g_kl[SEQ * DMOD];
__device__ bf16  g_vh[SEQ * DMOD], g_vl[SEQ * DMOD];

__device__ __forceinline__ void split_hl(float v, bf16& h, bf16& l) {
    h = __float2bfloat16(v);
    l = __float2bfloat16(v - __bfloat162float(h));
}

__device__ __forceinline__ void cp16b(bf16* dst, const bf16* src) {
    uint32_t s = (uint32_t)__cvta_generic_to_shared(dst);
    asm volatile("cp.async.cg.shared.global [%0], [%1], 16;\n" :: "r"(s), "l"(src));
}
__device__ __forceinline__ void cp16f(float* dst, const float* src) {
    uint32_t s = (uint32_t)__cvta_generic_to_shared(dst);
    asm volatile("cp.async.cg.shared.global [%0], [%1], 16;\n" :: "r"(s), "l"(src));
}

// ---------------- LayerNorm -> fp32 --------------------------------------------
__global__ void __launch_bounds__(256) ln_kernel(const float* __restrict__ x,
                                                 float* __restrict__ y) {
    __shared__ float row[DMOD];
    __shared__ float red[256];
    const int r   = blockIdx.x;
    const int tid = threadIdx.x;
    const float* xr = x + (long)r * DMOD;

    float s = 0.f;
    #pragma unroll
    for (int i = 0; i < 4; i++) {
        float v = xr[tid + i * 256];
        row[tid + i * 256] = v;
        s += v;
    }
    red[tid] = s; __syncthreads();
    #pragma unroll
    for (int off = 128; off > 0; off >>= 1) {
        if (tid < off) red[tid] += red[tid + off];
        __syncthreads();
    }
    const float mu = red[0] * (1.f / DMOD);
    __syncthreads();

    float ss = 0.f;
    #pragma unroll
    for (int i = 0; i < 4; i++) {
        float d = row[tid + i * 256] - mu;
        ss += d * d;
    }
    red[tid] = ss; __syncthreads();
    #pragma unroll
    for (int off = 128; off > 0; off >>= 1) {
        if (tid < off) red[tid] += red[tid + off];
        __syncthreads();
    }
    const float inv = rsqrtf(red[0] * (1.f / DMOD) + 1e-5f);

    float* yr = y + (long)r * DMOD;
    #pragma unroll
    for (int i = 0; i < 4; i++) {
        int c = tid + i * 256;
        yr[c] = (row[c] - mu) * inv;
    }
}

// ---------------- TF32 GEMM 128x128: single pass, cp.async 2-stage -------------
// C[M,N] = A[M,K](fp32 as tf32) * B[N,K]^T (+Res). wmma m16n16k8.
#define GBK    32
#define PADKF  36                                    // fp32 stride (144 B rows)
#define TF_STAGE (2 * 128 * PADKF)                   // floats per stage
#define TF_SMEM  (2 * TF_STAGE * (int)sizeof(float)) // 73728 B

__global__ void __launch_bounds__(256, 2) gemm_tf32(
    const float* __restrict__ A, int lda,
    const float* __restrict__ B, int ldb,
    float* __restrict__ C, int ldc, const float* __restrict__ Res, int K)
{
    extern __shared__ float smf[];
    const int tid  = threadIdx.x;
    const int m0   = blockIdx.y * 128;
    const int n0   = blockIdx.x * 128;
    const int warp = tid >> 5;
    const int wm0  = (warp & 3) * 32;
    const int wn0  = (warp >> 2) * 64;

    wmma::fragment<wmma::accumulator, 16, 16, 8, float> acc[2][4];
    #pragma unroll
    for (int i = 0; i < 2; i++)
        #pragma unroll
        for (int j = 0; j < 4; j++) {
            if (Res) {
                const float* rp = Res + (long)(m0 + wm0 + 16 * i) * ldc
                                      + n0 + wn0 + 16 * j;
                wmma::load_matrix_sync(acc[i][j], rp, ldc, wmma::mem_row_major);
            } else {
                wmma::fill_fragment(acc[i][j], 0.f);
            }
        }

    const float* Abase = A + (long)m0 * lda;
    const float* Bbase = B + (long)n0 * ldb;

    // per stage: A 128x32 fp32 (1024 x16B chunks) + B same -> 8 chunks/thread
    #define TF_LOAD(ST, K0)                                                    \
    do {                                                                       \
        float* sb = smf + (ST) * TF_STAGE;                                     \
        _Pragma("unroll")                                                      \
        for (int t = 0; t < 8; t++) {                                          \
            int c   = tid + t * 256;                                           \
            int arr = c >> 10;                                                 \
            int rem = c & 1023;                                                \
            int row = rem >> 3;                                                \
            int col = (rem & 7) * 4;                                           \
            const float* src = arr ? Bbase + (long)row * ldb + (K0) + col      \
                                   : Abase + (long)row * lda + (K0) + col;     \
            cp16f(sb + arr * (128 * PADKF) + row * PADKF + col, src);          \
        }                                                                      \
        asm volatile("cp.async.commit_group;\n" ::);                           \
    } while (0)

    const int nk = K / GBK;
    TF_LOAD(0, 0);

    for (int ks = 0; ks < nk; ks++) {
        asm volatile("cp.async.wait_group 0;\n" ::);
        __syncthreads();
        if (ks + 1 < nk) TF_LOAD((ks + 1) & 1, (ks + 1) * GBK);

        float* sb = smf + (ks & 1) * TF_STAGE;
        float* sA = sb;
        float* sB = sb + 128 * PADKF;

        #pragma unroll
        for (int k8 = 0; k8 < GBK; k8 += 8) {
            wmma::fragment<wmma::matrix_a, 16, 16, 8, wmma::precision::tf32,
                           wmma::row_major> af[2];
            #pragma unroll
            for (int i = 0; i < 2; i++) {
                wmma::load_matrix_sync(af[i], sA + (wm0 + 16 * i) * PADKF + k8, PADKF);
                #pragma unroll
                for (int t = 0; t < af[i].num_elements; t++)
                    af[i].x[t] = wmma::__float_to_tf32(af[i].x[t]);
            }
            #pragma unroll
            for (int j = 0; j < 4; j++) {
                wmma::fragment<wmma::matrix_b, 16, 16, 8, wmma::precision::tf32,
                               wmma::col_major> bfr;
                wmma::load_matrix_sync(bfr, sB + (wn0 + 16 * j) * PADKF + k8, PADKF);
                #pragma unroll
                for (int t = 0; t < bfr.num_elements; t++)
                    bfr.x[t] = wmma::__float_to_tf32(bfr.x[t]);
                #pragma unroll
                for (int i = 0; i < 2; i++)
                    wmma::mma_sync(acc[i][j], af[i], bfr, acc[i][j]);
            }
        }
    }

    #pragma unroll
    for (int i = 0; i < 2; i++)
        #pragma unroll
        for (int j = 0; j < 4; j++) {
            float* cp = C + (long)(m0 + wm0 + 16 * i) * ldc + n0 + wn0 + 16 * j;
            wmma::store_matrix_sync(cp, acc[i][j], ldc, wmma::mem_row_major);
        }
}

// ---------------- RoPE + head-major hi/lo split of q,k,v -----------------------
__global__ void __launch_bounds__(256) rope_split(
    const float* __restrict__ qkv,
    bf16* __restrict__ qh, bf16* __restrict__ ql,
    bf16* __restrict__ kh, bf16* __restrict__ kl,
    bf16* __restrict__ vh, bf16* __restrict__ vl)
{
    const int idx = blockIdx.x * 256 + threadIdx.x;   // SEQ*NHEAD*32
    if (idx >= SEQ * NHEAD * 32) return;
    const int j = idx & 31;
    const int h = (idx >> 5) & (NHEAD - 1);
    const int l = idx >> 9;

    const float inv_freq = powf(10000.f, -(float)j / 32.f);
    const float ang = (float)l * inv_freq;
    float c, s;
    sincosf(ang, &s, &c);

    const float* qp = qkv + (long)l * (3 * DMOD) + h * HDIM + j;
    const float q1 = qp[0], q2 = qp[32];
    const float k1 = qp[DMOD], k2 = qp[DMOD + 32];
    const float v1 = qp[2 * DMOD], v2 = qp[2 * DMOD + 32];

    const long dst = ((long)h * SEQ + l) * HDIM + j;
    split_hl((q1 * c - q2 * s) * 0.125f, qh[dst],      ql[dst]);
    split_hl((q2 * c + q1 * s) * 0.125f, qh[dst + 32], ql[dst + 32]);
    split_hl(k1 * c - k2 * s,            kh[dst],      kl[dst]);
    split_hl(k2 * c + k1 * s,            kh[dst + 32], kl[dst + 32]);
    split_hl(v1,                         vh[dst],      vl[dst]);
    split_hl(v2,                         vh[dst + 32], vl[dst + 32]);
}

// ---------------- Flash attention (bf16 3-pass, fp32 out) ----------------------
#define QSTR 80
#define FSTR 68
#define AT2_SMEM (4 * 64 * QSTR * 2 + 2 * 64 * FSTR * 4)   // 75776 B

__global__ void __launch_bounds__(256, 2) attn2(
    const bf16* __restrict__ Qh, const bf16* __restrict__ Ql,
    const bf16* __restrict__ Kh, const bf16* __restrict__ Kl,
    const bf16* __restrict__ Vh, const bf16* __restrict__ Vl,
    float* __restrict__ out)
{
    extern __shared__ char smraw[];
    bf16* sKh = (bf16*)smraw;
    bf16* sKl = sKh + 64 * QSTR;
    bf16* sVh = sKl + 64 * QSTR;
    bf16* sVl = sVh + 64 * QSTR;
    float* Sf = (float*)(sVl + 64 * QSTR);
    float* Of = Sf + 64 * FSTR;
    bf16* Ph = sKh;
    bf16* Pl = sKl;

    const int h     = blockIdx.x;
    const int qb    = (int)gridDim.y - 1 - (int)blockIdx.y;
    const int tid   = threadIdx.x;
    const int warp  = tid >> 5;
    const int qbase = qb * 64;
    const int rt    = warp >> 1;
    const int chalf = (warp & 1) * 32;

    const long qoff = ((long)h * SEQ + qbase) * HDIM;
    #pragma unroll
    for (int t = 0; t < 2; t++) {
        int c = tid + t * 256;
        int row = c >> 3, ch = (c & 7) * 8;
        cp16b(sKh + row * QSTR + ch, Qh + qoff + row * HDIM + ch);
        cp16b(sKl + row * QSTR + ch, Ql + qoff + row * HDIM + ch);
    }
    asm volatile("cp.async.commit_group;\n" ::);
    asm volatile("cp.async.wait_group 0;\n" ::);
    __syncthreads();

    wmma::fragment<wmma::matrix_a, 16, 16, 16, bf16, wmma::row_major> qhf[4], qlf[4];
    #pragma unroll
    for (int ks = 0; ks < 4; ks++) {
        wmma::load_matrix_sync(qhf[ks], sKh + rt * 16 * QSTR + ks * 16, QSTR);
        wmma::load_matrix_sync(qlf[ks], sKl + rt * 16 * QSTR + ks * 16, QSTR);
    }
    for (int i = tid; i < 64 * FSTR; i += 256) Of[i] = 0.f;
    __syncthreads();

    const int r  = tid >> 2;
    const int cs = (tid & 3) * 16;
    float mrow = -1e30f, lsum = 0.f, alpha = 0.f;

    for (int kb = 0; kb <= qb; kb++) {
        const long koff = ((long)h * SEQ + kb * 64) * HDIM;
        #pragma unroll
        for (int t = 0; t < 2; t++) {
            int c = tid + t * 256;
            int row = c >> 3, ch = (c & 7) * 8;
            cp16b(sKh + row * QSTR + ch, Kh + koff + row * HDIM + ch);
            cp16b(sKl + row * QSTR + ch, Kl + koff + row * HDIM + ch);
            cp16b(sVh + row * QSTR + ch, Vh + koff + row * HDIM + ch);
            cp16b(sVl + row * QSTR + ch, Vl + koff + row * HDIM + ch);
        }
        asm volatile("cp.async.commit_group;\n" ::);
        asm volatile("cp.async.wait_group 0;\n" ::);
        __syncthreads();

        #pragma unroll
        for (int ct = 0; ct < 2; ct++) {
            const int col0 = chalf + ct * 16;
            wmma::fragment<wmma::accumulator, 16, 16, 16, float> acc;
            wmma::fill_fragment(acc, 0.f);
            #pragma unroll
            for (int ks = 0; ks < 4; ks++) {
                wmma::fragment<wmma::matrix_b, 16, 16, 16, bf16, wmma::col_major> bh, bl;
                wmma::load_matrix_sync(bh, sKh + col0 * QSTR + ks * 16, QSTR);
                wmma::load_matrix_sync(bl, sKl + col0 * QSTR + ks * 16, QSTR);
                wmma::mma_sync(acc, qhf[ks], bl, acc);
                wmma::mma_sync(acc, qlf[ks], bh, acc);
                wmma::mma_sync(acc, qhf[ks], bh, acc);
            }
            wmma::store_matrix_sync(Sf + rt * 16 * FSTR + col0, acc, FSTR,
                                    wmma::mem_row_major);
        }
        __syncthreads();

        float s[16];
        #pragma unroll
        for (int j = 0; j < 16; j++) s[j] = Sf[r * FSTR + cs + j];
        if (kb == qb) {
            const int kbase = kb * 64;
            #pragma unroll
            for (int j = 0; j < 16; j++)
                if (kbase + cs + j > qbase + r) s[j] = -1e30f;
        }
        float mloc = s[0];
        #pragma unroll
        for (int j = 1; j < 16; j++) mloc = fmaxf(mloc, s[j]);
        mloc = fmaxf(mloc, __shfl_xor_sync(0xffffffffu, mloc, 1));
        mloc = fmaxf(mloc, __shfl_xor_sync(0xffffffffu, mloc, 2));
        const float mnew = fmaxf(mrow, mloc);
        alpha = __expf(mrow - mnew);

        float ps = 0.f;
        #pragma unroll
        for (int j = 0; j < 16; j++) {
            float p = __expf(s[j] - mnew);
            ps += p;
            split_hl(p, Ph[r * QSTR + cs + j], Pl[r * QSTR + cs + j]);
        }
        ps += __shfl_xor_sync(0xffffffffu, ps, 1);
        ps += __shfl_xor_sync(0xffffffffu, ps, 2);
        lsum = lsum * alpha + ps;
        mrow = mnew;
        __syncthreads();

        #pragma unroll
        for (int ct = 0; ct < 2; ct++) {
            const int col0 = chalf + ct * 16;
            wmma::fragment<wmma::accumulator, 16, 16, 16, float> acc;
            wmma::fill_fragment(acc, 0.f);
            #pragma unroll
            for (int js = 0; js < 4; js++) {
                wmma::fragment<wmma::matrix_a, 16, 16, 16, bf16, wmma::row_major> ph, pl;
                wmma::load_matrix_sync(ph, Ph + rt * 16 * QSTR + js * 16, QSTR);
                wmma::load_matrix_sync(pl, Pl + rt * 16 * QSTR + js * 16, QSTR);
                wmma::fragment<wmma::matrix_b, 16, 16, 16, bf16, wmma::row_major> vh, vl;
                wmma::load_matrix_sync(vh, sVh + js * 16 * QSTR + col0, QSTR);
                wmma::load_matrix_sync(vl, sVl + js * 16 * QSTR + col0, QSTR);
                wmma::mma_sync(acc, ph, vl, acc);
                wmma::mma_sync(acc, pl, vh, acc);
                wmma::mma_sync(acc, ph, vh, acc);
            }
            wmma::store_matrix_sync(Sf + rt * 16 * FSTR + col0, acc, FSTR,
                                    wmma::mem_row_major);
        }
        __syncthreads();

        #pragma unroll
        for (int j = 0; j < 16; j++) {
            int o = r * FSTR + cs + j;
            Of[o] = Of[o] * alpha + Sf[o];
        }
        __syncthreads();
    }

    const float invl = 1.f / lsum;
    float* orow = out + (long)(qbase + r) * DMOD + h * HDIM + cs;
    #pragma unroll
    for (int j = 0; j < 16; j++) orow[j] = Of[r * FSTR + cs + j] * invl;
}

// ---------------- SwiGLU -> fp32 ------------------------------------------------
__global__ void __launch_bounds__(256) swiglu_kernel(const float* __restrict__ g,
                                                     float* __restrict__ o) {
    const int idx = blockIdx.x * 256 + threadIdx.x;
    if (idx >= SEQ * (DMLP / 2)) return;
    const int rw = idx >> 12;
    const int c  = idx & 4095;
    const float x1 = g[(long)rw * DMLP + c];
    const float x2 = g[(long)rw * DMLP + (DMLP / 2) + c];
    const float sig = 1.f / (1.f + __expf(-x2));
    o[idx] = x2 * sig * x1;
}

// ---------------- launch ---------------------------------------------------------
extern "C" void kernel_launch(void* const* d_in, const int* in_sizes, int n_in,
                              void* d_out, int out_size) {
    const float* x      = (const float*)d_in[0];
    const float* W_attn = (const float*)d_in[2];
    const float* W_out  = (const float*)d_in[3];
    const float* W_ffp  = (const float*)d_in[4];
    const float* W_ffo  = (const float*)d_in[5];
    float* out = (float*)d_out;

    float *xn, *qkv, *attn, *h, *hn, *gbuf, *mlp;
    bf16 *qh, *ql, *kh, *kl, *vh, *vl;
    cudaGetSymbolAddress((void**)&xn,  g_xn);
    cudaGetSymbolAddress((void**)&qkv, g_qkv);
    cudaGetSymbolAddress((void**)&attn,g_attn);
    cudaGetSymbolAddress((void**)&h,   g_h);
    cudaGetSymbolAddress((void**)&hn,  g_hn);
    cudaGetSymbolAddress((void**)&gbuf,g_g);
    cudaGetSymbolAddress((void**)&mlp, g_mlp);
    cudaGetSymbolAddress((void**)&qh,  g_qh);  cudaGetSymbolAddress((void**)&ql,  g_ql);
    cudaGetSymbolAddress((void**)&kh,  g_kh);  cudaGetSymbolAddress((void**)&kl,  g_kl);
    cudaGetSymbolAddress((void**)&vh,  g_vh);  cudaGetSymbolAddress((void**)&vl,  g_vl);

    cudaFuncSetAttribute(attn2,
                         cudaFuncAttributeMaxDynamicSharedMemorySize, AT2_SMEM);
    cudaFuncSetAttribute(gemm_tf32,
                         cudaFuncAttributeMaxDynamicSharedMemorySize, TF_SMEM);

    // 1) xn = LN(x)
    ln_kernel<<<SEQ, 256>>>(x, xn);

    // 2) qkv = xn @ W_attn^T
    gemm_tf32<<<dim3(3 * DMOD / 128, SEQ / 128), 256, TF_SMEM>>>(
        xn, DMOD, W_attn, DMOD, qkv, 3 * DMOD, nullptr, DMOD);

    // 3) RoPE + head-major hi/lo split
    rope_split<<<(SEQ * NHEAD * 32 + 255) / 256, 256>>>(qkv, qh, ql, kh, kl, vh, vl);

    // 4) attention -> fp32
    attn2<<<dim3(NHEAD, SEQ / 64), 256, AT2_SMEM>>>(qh, ql, kh, kl, vh, vl, attn);

    // 5) h = attn @ W_out^T + x
    gemm_tf32<<<dim3(DMOD / 128, SEQ / 128), 256, TF_SMEM>>>(
        attn, DMOD, W_out, DMOD, h, DMOD, x, DMOD);

    // 6) hn = LN(h)
    ln_kernel<<<SEQ, 256>>>(h, hn);

    // 7) g = hn @ W_ffp^T
    gemm_tf32<<<dim3(DMLP / 128, SEQ / 128), 256, TF_SMEM>>>(
        hn, DMOD, W_ffp, DMOD, gbuf, DMLP, nullptr, DMOD);

    // 8) mlp = silu(g2)*g1
    swiglu_kernel<<<(SEQ * (DMLP / 2) + 255) / 256, 256>>>(gbuf, mlp);

    // 9) out = mlp @ W_ffo^T + h
    gemm_tf32<<<dim3(DMOD / 128, SEQ / 128), 256, TF_SMEM>>>(
        mlp, DMLP / 2, W_ffo, DMLP / 2, out, DMOD, h, DMLP / 2);
}

// round 12
// speedup vs baseline: 2.4047x; 2.4047x over previous
#include <cuda_runtime.h>
#include <cuda_bf16.h>
#include <cuda_fp16.h>
#include <mma.h>
#include <math.h>
#include <cstdint>

using namespace nvcuda;
typedef __nv_bfloat16 bf16;

#define SEQ   2048
#define DMOD  1024
#define NHEAD 16
#define HDIM  64
#define DMLP  8192

// ---------------- scratch -----------------------------------------------------
__device__ float  g_qkv [SEQ * 3 * DMOD];
__device__ float  g_h   [SEQ * DMOD];
__device__ float  g_g   [SEQ * DMLP];
__device__ __half g_xn16 [SEQ * DMOD];
__device__ __half g_at16 [SEQ * DMOD];
__device__ __half g_hn16 [SEQ * DMOD];
__device__ __half g_mlp16[SEQ * (DMLP / 2)];
__device__ __half g_Wa16[3 * DMOD * DMOD];
__device__ __half g_Wo16[DMOD * DMOD];
__device__ __half g_Wp16[DMLP * DMOD];
__device__ __half g_Wf16[DMOD * DMLP / 2];
// head-major RoPE'd q/k/v, bf16 hi/lo:  [h][l][64]
__device__ bf16   g_qh[SEQ * DMOD], g_ql[SEQ * DMOD];
__device__ bf16   g_kh[SEQ * DMOD], g_kl[SEQ * DMOD];
__device__ bf16   g_vh[SEQ * DMOD], g_vl[SEQ * DMOD];

__device__ __forceinline__ void split_hl(float v, bf16& h, bf16& l) {
    h = __float2bfloat16(v);
    l = __float2bfloat16(v - __bfloat162float(h));
}

__device__ __forceinline__ void cp16b(bf16* dst, const bf16* src) {
    uint32_t s = (uint32_t)__cvta_generic_to_shared(dst);
    asm volatile("cp.async.cg.shared.global [%0], [%1], 16;\n" :: "r"(s), "l"(src));
}
__device__ __forceinline__ void cp16h(__half* dst, const __half* src) {
    uint32_t s = (uint32_t)__cvta_generic_to_shared(dst);
    asm volatile("cp.async.cg.shared.global [%0], [%1], 16;\n" :: "r"(s), "l"(src));
}

// ---------------- fp32 -> fp16 convert (vectorized) -----------------------------
__global__ void __launch_bounds__(256) cvt_h(const float* __restrict__ s,
                                             __half* __restrict__ d, int n) {
    int i = (blockIdx.x * 256 + threadIdx.x) * 8;
    if (i >= n) return;
    float4 v0 = *(const float4*)(s + i);
    float4 v1 = *(const float4*)(s + i + 4);
    float a[8] = {v0.x, v0.y, v0.z, v0.w, v1.x, v1.y, v1.z, v1.w};
    __align__(16) __half hh[8];
    #pragma unroll
    for (int e = 0; e < 8; e++) hh[e] = __float2half_rn(a[e]);
    *(uint4*)(d + i) = *(uint4*)hh;
}

// ---------------- LayerNorm -> fp16 ---------------------------------------------
__global__ void __launch_bounds__(256) ln_kernel(const float* __restrict__ x,
                                                 __half* __restrict__ y) {
    __shared__ float row[DMOD];
    __shared__ float red[256];
    const int r   = blockIdx.x;
    const int tid = threadIdx.x;
    const float* xr = x + (long)r * DMOD;

    float s = 0.f;
    #pragma unroll
    for (int i = 0; i < 4; i++) {
        float v = xr[tid + i * 256];
        row[tid + i * 256] = v;
        s += v;
    }
    red[tid] = s; __syncthreads();
    #pragma unroll
    for (int off = 128; off > 0; off >>= 1) {
        if (tid < off) red[tid] += red[tid + off];
        __syncthreads();
    }
    const float mu = red[0] * (1.f / DMOD);
    __syncthreads();

    float ss = 0.f;
    #pragma unroll
    for (int i = 0; i < 4; i++) {
        float d = row[tid + i * 256] - mu;
        ss += d * d;
    }
    red[tid] = ss; __syncthreads();
    #pragma unroll
    for (int off = 128; off > 0; off >>= 1) {
        if (tid < off) red[tid] += red[tid + off];
        __syncthreads();
    }
    const float inv = rsqrtf(red[0] * (1.f / DMOD) + 1e-5f);

    __half* yr = y + (long)r * DMOD;
    #pragma unroll
    for (int i = 0; i < 4; i++) {
        int c = tid + i * 256;
        yr[c] = __float2half_rn((row[c] - mu) * inv);
    }
}

// ---------------- fp16 GEMM 128x128: single pass, cp.async 2-stage --------------
#define GBK   32
#define PADK  40
#define GH_SMEM (2 * 2 * 128 * PADK * (int)sizeof(__half))   // 40960 B

__global__ void __launch_bounds__(256, 2) gemm_h(
    const __half* __restrict__ A, int lda,
    const __half* __restrict__ B, int ldb,
    float* __restrict__ C, int ldc, const float* __restrict__ Res, int K)
{
    extern __shared__ __half smh[];
    const int tid  = threadIdx.x;
    const int m0   = blockIdx.y * 128;
    const int n0   = blockIdx.x * 128;
    const int warp = tid >> 5;
    const int wm0  = (warp & 3) * 32;
    const int wn0  = (warp >> 2) * 64;

    wmma::fragment<wmma::accumulator, 16, 16, 16, float> acc[2][4];
    #pragma unroll
    for (int i = 0; i < 2; i++)
        #pragma unroll
        for (int j = 0; j < 4; j++) {
            if (Res) {
                const float* rp = Res + (long)(m0 + wm0 + 16 * i) * ldc
                                      + n0 + wn0 + 16 * j;
                wmma::load_matrix_sync(acc[i][j], rp, ldc, wmma::mem_row_major);
            } else {
                wmma::fill_fragment(acc[i][j], 0.f);
            }
        }

    const __half* Abase = A + (long)m0 * lda;
    const __half* Bbase = B + (long)n0 * ldb;

    // per stage: A 128x32 (512 chunks) + B 128x32 (512) -> 4 chunks/thread
    #define GH_LOAD(ST, K0)                                                    \
    do {                                                                       \
        __half* sb = smh + (ST) * (2 * 128 * PADK);                            \
        _Pragma("unroll")                                                      \
        for (int t = 0; t < 4; t++) {                                          \
            int c   = tid + t * 256;                                           \
            int arr = c >> 9;                                                  \
            int rem = c & 511;                                                 \
            int row = rem >> 2;                                                \
            int col = (rem & 3) * 8;                                           \
            const __half* src = arr ? Bbase + (long)row * ldb + (K0) + col     \
                                    : Abase + (long)row * lda + (K0) + col;    \
            cp16h(sb + arr * (128 * PADK) + row * PADK + col, src);            \
        }                                                                      \
        asm volatile("cp.async.commit_group;\n" ::);                           \
    } while (0)

    const int nk = K / GBK;
    GH_LOAD(0, 0);

    for (int ks = 0; ks < nk; ks++) {
        asm volatile("cp.async.wait_group 0;\n" ::);
        __syncthreads();
        if (ks + 1 < nk) GH_LOAD((ks + 1) & 1, (ks + 1) * GBK);

        __half* sb = smh + (ks & 1) * (2 * 128 * PADK);
        __half* sA = sb;
        __half* sB = sb + 128 * PADK;

        #pragma unroll
        for (int k16 = 0; k16 < GBK; k16 += 16) {
            wmma::fragment<wmma::matrix_a, 16, 16, 16, __half, wmma::row_major> af[2];
            #pragma unroll
            for (int i = 0; i < 2; i++)
                wmma::load_matrix_sync(af[i], sA + (wm0 + 16 * i) * PADK + k16, PADK);
            #pragma unroll
            for (int j = 0; j < 4; j++) {
                wmma::fragment<wmma::matrix_b, 16, 16, 16, __half, wmma::col_major> bfr;
                wmma::load_matrix_sync(bfr, sB + (wn0 + 16 * j) * PADK + k16, PADK);
                #pragma unroll
                for (int i = 0; i < 2; i++)
                    wmma::mma_sync(acc[i][j], af[i], bfr, acc[i][j]);
            }
        }
    }

    #pragma unroll
    for (int i = 0; i < 2; i++)
        #pragma unroll
        for (int j = 0; j < 4; j++) {
            float* cp = C + (long)(m0 + wm0 + 16 * i) * ldc + n0 + wn0 + 16 * j;
            wmma::store_matrix_sync(cp, acc[i][j], ldc, wmma::mem_row_major);
        }
}

// ---------------- RoPE + head-major hi/lo split of q,k,v ------------------------
__global__ void __launch_bounds__(256) rope_split(
    const float* __restrict__ qkv,
    bf16* __restrict__ qh, bf16* __restrict__ ql,
    bf16* __restrict__ kh, bf16* __restrict__ kl,
    bf16* __restrict__ vh, bf16* __restrict__ vl)
{
    const int idx = blockIdx.x * 256 + threadIdx.x;
    if (idx >= SEQ * NHEAD * 32) return;
    const int j = idx & 31;
    const int h = (idx >> 5) & (NHEAD - 1);
    const int l = idx >> 9;

    const float inv_freq = powf(10000.f, -(float)j / 32.f);
    const float ang = (float)l * inv_freq;
    float c, s;
    sincosf(ang, &s, &c);

    const float* qp = qkv + (long)l * (3 * DMOD) + h * HDIM + j;
    const float q1 = qp[0], q2 = qp[32];
    const float k1 = qp[DMOD], k2 = qp[DMOD + 32];
    const float v1 = qp[2 * DMOD], v2 = qp[2 * DMOD + 32];

    const long dst = ((long)h * SEQ + l) * HDIM + j;
    split_hl((q1 * c - q2 * s) * 0.125f, qh[dst],      ql[dst]);
    split_hl((q2 * c + q1 * s) * 0.125f, qh[dst + 32], ql[dst + 32]);
    split_hl(k1 * c - k2 * s,            kh[dst],      kl[dst]);
    split_hl(k2 * c + k1 * s,            kh[dst + 32], kl[dst + 32]);
    split_hl(v1,                         vh[dst],      vl[dst]);
    split_hl(v2,                         vh[dst + 32], vl[dst + 32]);
}

// ---------------- Flash attention (bf16 3-pass, fp16 out) -----------------------
#define QSTR 80
#define FSTR 68
#define AT2_SMEM (4 * 64 * QSTR * 2 + 2 * 64 * FSTR * 4)   // 75776 B

__global__ void __launch_bounds__(256, 2) attn2(
    const bf16* __restrict__ Qh, const bf16* __restrict__ Ql,
    const bf16* __restrict__ Kh, const bf16* __restrict__ Kl,
    const bf16* __restrict__ Vh, const bf16* __restrict__ Vl,
    __half* __restrict__ out)
{
    extern __shared__ char smraw[];
    bf16* sKh = (bf16*)smraw;
    bf16* sKl = sKh + 64 * QSTR;
    bf16* sVh = sKl + 64 * QSTR;
    bf16* sVl = sVh + 64 * QSTR;
    float* Sf = (float*)(sVl + 64 * QSTR);
    float* Of = Sf + 64 * FSTR;
    bf16* Ph = sKh;
    bf16* Pl = sKl;

    const int h     = blockIdx.x;
    const int qb    = (int)gridDim.y - 1 - (int)blockIdx.y;
    const int tid   = threadIdx.x;
    const int warp  = tid >> 5;
    const int qbase = qb * 64;
    const int rt    = warp >> 1;
    const int chalf = (warp & 1) * 32;

    const long qoff = ((long)h * SEQ + qbase) * HDIM;
    #pragma unroll
    for (int t = 0; t < 2; t++) {
        int c = tid + t * 256;
        int row = c >> 3, ch = (c & 7) * 8;
        cp16b(sKh + row * QSTR + ch, Qh + qoff + row * HDIM + ch);
        cp16b(sKl + row * QSTR + ch, Ql + qoff + row * HDIM + ch);
    }
    asm volatile("cp.async.commit_group;\n" ::);
    asm volatile("cp.async.wait_group 0;\n" ::);
    __syncthreads();

    wmma::fragment<wmma::matrix_a, 16, 16, 16, bf16, wmma::row_major> qhf[4], qlf[4];
    #pragma unroll
    for (int ks = 0; ks < 4; ks++) {
        wmma::load_matrix_sync(qhf[ks], sKh + rt * 16 * QSTR + ks * 16, QSTR);
        wmma::load_matrix_sync(qlf[ks], sKl + rt * 16 * QSTR + ks * 16, QSTR);
    }
    for (int i = tid; i < 64 * FSTR; i += 256) Of[i] = 0.f;
    __syncthreads();

    const int r  = tid >> 2;
    const int cs = (tid & 3) * 16;
    float mrow = -1e30f, lsum = 0.f, alpha = 0.f;

    for (int kb = 0; kb <= qb; kb++) {
        const long koff = ((long)h * SEQ + kb * 64) * HDIM;
        #pragma unroll
        for (int t = 0; t < 2; t++) {
            int c = tid + t * 256;
            int row = c >> 3, ch = (c & 7) * 8;
            cp16b(sKh + row * QSTR + ch, Kh + koff + row * HDIM + ch);
            cp16b(sKl + row * QSTR + ch, Kl + koff + row * HDIM + ch);
            cp16b(sVh + row * QSTR + ch, Vh + koff + row * HDIM + ch);
            cp16b(sVl + row * QSTR + ch, Vl + koff + row * HDIM + ch);
        }
        asm volatile("cp.async.commit_group;\n" ::);
        asm volatile("cp.async.wait_group 0;\n" ::);
        __syncthreads();

        #pragma unroll
        for (int ct = 0; ct < 2; ct++) {
            const int col0 = chalf + ct * 16;
            wmma::fragment<wmma::accumulator, 16, 16, 16, float> acc;
            wmma::fill_fragment(acc, 0.f);
            #pragma unroll
            for (int ks = 0; ks < 4; ks++) {
                wmma::fragment<wmma::matrix_b, 16, 16, 16, bf16, wmma::col_major> bh, bl;
                wmma::load_matrix_sync(bh, sKh + col0 * QSTR + ks * 16, QSTR);
                wmma::load_matrix_sync(bl, sKl + col0 * QSTR + ks * 16, QSTR);
                wmma::mma_sync(acc, qhf[ks], bl, acc);
                wmma::mma_sync(acc, qlf[ks], bh, acc);
                wmma::mma_sync(acc, qhf[ks], bh, acc);
            }
            wmma::store_matrix_sync(Sf + rt * 16 * FSTR + col0, acc, FSTR,
                                    wmma::mem_row_major);
        }
        __syncthreads();

        float s[16];
        #pragma unroll
        for (int j = 0; j < 16; j++) s[j] = Sf[r * FSTR + cs + j];
        if (kb == qb) {
            const int kbase = kb * 64;
            #pragma unroll
            for (int j = 0; j < 16; j++)
                if (kbase + cs + j > qbase + r) s[j] = -1e30f;
        }
        float mloc = s[0];
        #pragma unroll
        for (int j = 1; j < 16; j++) mloc = fmaxf(mloc, s[j]);
        mloc = fmaxf(mloc, __shfl_xor_sync(0xffffffffu, mloc, 1));
        mloc = fmaxf(mloc, __shfl_xor_sync(0xffffffffu, mloc, 2));
        const float mnew = fmaxf(mrow, mloc);
        alpha = __expf(mrow - mnew);

        float ps = 0.f;
        #pragma unroll
        for (int j = 0; j < 16; j++) {
            float p = __expf(s[j] - mnew);
            ps += p;
            split_hl(p, Ph[r * QSTR + cs + j], Pl[r * QSTR + cs + j]);
        }
        ps += __shfl_xor_sync(0xffffffffu, ps, 1);
        ps += __shfl_xor_sync(0xffffffffu, ps, 2);
        lsum = lsum * alpha + ps;
        mrow = mnew;
        __syncthreads();

        #pragma unroll
        for (int ct = 0; ct < 2; ct++) {
            const int col0 = chalf + ct * 16;
            wmma::fragment<wmma::accumulator, 16, 16, 16, float> acc;
            wmma::fill_fragment(acc, 0.f);
            #pragma unroll
            for (int js = 0; js < 4; js++) {
                wmma::fragment<wmma::matrix_a, 16, 16, 16, bf16, wmma::row_major> ph, pl;
                wmma::load_matrix_sync(ph, Ph + rt * 16 * QSTR + js * 16, QSTR);
                wmma::load_matrix_sync(pl, Pl + rt * 16 * QSTR + js * 16, QSTR);
                wmma::fragment<wmma::matrix_b, 16, 16, 16, bf16, wmma::row_major> vh, vl;
                wmma::load_matrix_sync(vh, sVh + js * 16 * QSTR + col0, QSTR);
                wmma::load_matrix_sync(vl, sVl + js * 16 * QSTR + col0, QSTR);
                wmma::mma_sync(acc, ph, vl, acc);
                wmma::mma_sync(acc, pl, vh, acc);
                wmma::mma_sync(acc, ph, vh, acc);
            }
            wmma::store_matrix_sync(Sf + rt * 16 * FSTR + col0, acc, FSTR,
                                    wmma::mem_row_major);
        }
        __syncthreads();

        #pragma unroll
        for (int j = 0; j < 16; j++) {
            int o = r * FSTR + cs + j;
            Of[o] = Of[o] * alpha + Sf[o];
        }
        __syncthreads();
    }

    const float invl = 1.f / lsum;
    __half* orow = out + (long)(qbase + r) * DMOD + h * HDIM + cs;
    #pragma unroll
    for (int j = 0; j < 16; j++)
        orow[j] = __float2half_rn(Of[r * FSTR + cs + j] * invl);
}

// ---------------- SwiGLU -> fp16 -------------------------------------------------
__global__ void __launch_bounds__(256) swiglu_kernel(const float* __restrict__ g,
                                                     __half* __restrict__ o) {
    const int idx = blockIdx.x * 256 + threadIdx.x;
    if (idx >= SEQ * (DMLP / 2)) return;
    const int rw = idx >> 12;
    const int c  = idx & 4095;
    const float x1 = g[(long)rw * DMLP + c];
    const float x2 = g[(long)rw * DMLP + (DMLP / 2) + c];
    const float sig = 1.f / (1.f + __expf(-x2));
    o[idx] = __float2half_rn(x2 * sig * x1);
}

// ---------------- launch ----------------------------------------------------------
extern "C" void kernel_launch(void* const* d_in, const int* in_sizes, int n_in,
                              void* d_out, int out_size) {
    const float* x      = (const float*)d_in[0];
    const float* W_attn = (const float*)d_in[2];
    const float* W_out  = (const float*)d_in[3];
    const float* W_ffp  = (const float*)d_in[4];
    const float* W_ffo  = (const float*)d_in[5];
    float* out = (float*)d_out;

    float *qkv, *h, *gbuf;
    __half *xn16, *at16, *hn16, *mlp16, *Wa16, *Wo16, *Wp16, *Wf16;
    bf16 *qh, *ql, *kh, *kl, *vh, *vl;
    cudaGetSymbolAddress((void**)&qkv,  g_qkv);
    cudaGetSymbolAddress((void**)&h,    g_h);
    cudaGetSymbolAddress((void**)&gbuf, g_g);
    cudaGetSymbolAddress((void**)&xn16, g_xn16);
    cudaGetSymbolAddress((void**)&at16, g_at16);
    cudaGetSymbolAddress((void**)&hn16, g_hn16);
    cudaGetSymbolAddress((void**)&mlp16,g_mlp16);
    cudaGetSymbolAddress((void**)&Wa16, g_Wa16);
    cudaGetSymbolAddress((void**)&Wo16, g_Wo16);
    cudaGetSymbolAddress((void**)&Wp16, g_Wp16);
    cudaGetSymbolAddress((void**)&Wf16, g_Wf16);
    cudaGetSymbolAddress((void**)&qh, g_qh); cudaGetSymbolAddress((void**)&ql, g_ql);
    cudaGetSymbolAddress((void**)&kh, g_kh); cudaGetSymbolAddress((void**)&kl, g_kl);
    cudaGetSymbolAddress((void**)&vh, g_vh); cudaGetSymbolAddress((void**)&vl, g_vl);

    cudaFuncSetAttribute(attn2,
                         cudaFuncAttributeMaxDynamicSharedMemorySize, AT2_SMEM);
    cudaFuncSetAttribute(gemm_h,
                         cudaFuncAttributeMaxDynamicSharedMemorySize, GH_SMEM);

    // weight converts (one array each)
    { int n = 3 * DMOD * DMOD; cvt_h<<<n / 8 / 256, 256>>>(W_attn, Wa16, n); }
    { int n = DMOD * DMOD;     cvt_h<<<n / 8 / 256, 256>>>(W_out,  Wo16, n); }
    { int n = DMLP * DMOD;     cvt_h<<<n / 8 / 256, 256>>>(W_ffp,  Wp16, n); }
    { int n = DMOD * DMLP / 2; cvt_h<<<n / 8 / 256, 256>>>(W_ffo,  Wf16, n); }

    // 1) xn = LN(x) -> fp16
    ln_kernel<<<SEQ, 256>>>(x, xn16);

    // 2) qkv = xn @ W_attn^T
    gemm_h<<<dim3(3 * DMOD / 128, SEQ / 128), 256, GH_SMEM>>>(
        xn16, DMOD, Wa16, DMOD, qkv, 3 * DMOD, nullptr, DMOD);

    // 3) RoPE + head-major hi/lo split (bf16, attention-internal)
    rope_split<<<(SEQ * NHEAD * 32 + 255) / 256, 256>>>(qkv, qh, ql, kh, kl, vh, vl);

    // 4) attention -> fp16
    attn2<<<dim3(NHEAD, SEQ / 64), 256, AT2_SMEM>>>(qh, ql, kh, kl, vh, vl, at16);

    // 5) h = attn @ W_out^T + x
    gemm_h<<<dim3(DMOD / 128, SEQ / 128), 256, GH_SMEM>>>(
        at16, DMOD, Wo16, DMOD, h, DMOD, x, DMOD);

    // 6) hn = LN(h) -> fp16
    ln_kernel<<<SEQ, 256>>>(h, hn16);

    // 7) g = hn @ W_ffp^T
    gemm_h<<<dim3(DMLP / 128, SEQ / 128), 256, GH_SMEM>>>(
        hn16, DMOD, Wp16, DMOD, gbuf, DMLP, nullptr, DMOD);

    // 8) mlp = silu(g2)*g1 -> fp16
    swiglu_kernel<<<(SEQ * (DMLP / 2) + 255) / 256, 256>>>(gbuf, mlp16);

    // 9) out = mlp @ W_ffo^T + h
    gemm_h<<<dim3(DMOD / 128, SEQ / 128), 256, GH_SMEM>>>(
        mlp16, DMLP / 2, Wf16, DMLP / 2, out, DMOD, h, DMLP / 2);
}

// round 13
// speedup vs baseline: 2.7329x; 1.1365x over previous
#include <cuda_runtime.h>
#include <cuda_bf16.h>
#include <cuda_fp16.h>
#include <mma.h>
#include <math.h>
#include <cstdint>

using namespace nvcuda;
typedef __nv_bfloat16 bf16;

#define SEQ   2048
#define DMOD  1024
#define NHEAD 16
#define HDIM  64
#define DMLP  8192

// ---------------- scratch -----------------------------------------------------
__device__ float  g_qkv [SEQ * 3 * DMOD];
__device__ float  g_h   [SEQ * DMOD];
__device__ float  g_g   [SEQ * DMLP];
__device__ __half g_xn16 [SEQ * DMOD];
__device__ __half g_at16 [SEQ * DMOD];
__device__ __half g_hn16 [SEQ * DMOD];
__device__ __half g_mlp16[SEQ * (DMLP / 2)];
__device__ __half g_Wa16[3 * DMOD * DMOD];
__device__ __half g_Wo16[DMOD * DMOD];
__device__ __half g_Wp16[DMLP * DMOD];
__device__ __half g_Wf16[DMOD * DMLP / 2];
// head-major RoPE'd q/k (bf16 hi/lo) and v (fp16):  [h][l][64]
__device__ bf16   g_qh[SEQ * DMOD], g_ql[SEQ * DMOD];
__device__ bf16   g_kh[SEQ * DMOD], g_kl[SEQ * DMOD];
__device__ __half g_v16[SEQ * DMOD];

__device__ __forceinline__ void split_hl(float v, bf16& h, bf16& l) {
    h = __float2bfloat16(v);
    l = __float2bfloat16(v - __bfloat162float(h));
}

__device__ __forceinline__ void cp16b(bf16* dst, const bf16* src) {
    uint32_t s = (uint32_t)__cvta_generic_to_shared(dst);
    asm volatile("cp.async.cg.shared.global [%0], [%1], 16;\n" :: "r"(s), "l"(src));
}
__device__ __forceinline__ void cp16h(__half* dst, const __half* src) {
    uint32_t s = (uint32_t)__cvta_generic_to_shared(dst);
    asm volatile("cp.async.cg.shared.global [%0], [%1], 16;\n" :: "r"(s), "l"(src));
}

// ---------------- fused fp32 -> fp16 convert for all 4 weights -----------------
__global__ void __launch_bounds__(256) cvt_all(
    const float* __restrict__ s0, __half* __restrict__ d0, int n0,
    const float* __restrict__ s1, __half* __restrict__ d1, int n1,
    const float* __restrict__ s2, __half* __restrict__ d2, int n2,
    const float* __restrict__ s3, __half* __restrict__ d3, int n3)
{
    long i = ((long)blockIdx.x * 256 + threadIdx.x) * 8;
    const float* s; __half* d; long off = i;
    if (off < n0)              { s = s0; d = d0; }
    else if ((off -= n0) < n1) { s = s1; d = d1; }
    else if ((off -= n1) < n2) { s = s2; d = d2; }
    else if ((off -= n2) < n3) { s = s3; d = d3; }
    else return;
    float4 v0 = *(const float4*)(s + off);
    float4 v1 = *(const float4*)(s + off + 4);
    float a[8] = {v0.x, v0.y, v0.z, v0.w, v1.x, v1.y, v1.z, v1.w};
    __align__(16) __half hh[8];
    #pragma unroll
    for (int e = 0; e < 8; e++) hh[e] = __float2half_rn(a[e]);
    *(uint4*)(d + off) = *(uint4*)hh;
}

// ---------------- LayerNorm -> fp16 ---------------------------------------------
__global__ void __launch_bounds__(256) ln_kernel(const float* __restrict__ x,
                                                 __half* __restrict__ y) {
    __shared__ float row[DMOD];
    __shared__ float red[256];
    const int r   = blockIdx.x;
    const int tid = threadIdx.x;
    const float* xr = x + (long)r * DMOD;

    float s = 0.f;
    #pragma unroll
    for (int i = 0; i < 4; i++) {
        float v = xr[tid + i * 256];
        row[tid + i * 256] = v;
        s += v;
    }
    red[tid] = s; __syncthreads();
    #pragma unroll
    for (int off = 128; off > 0; off >>= 1) {
        if (tid < off) red[tid] += red[tid + off];
        __syncthreads();
    }
    const float mu = red[0] * (1.f / DMOD);
    __syncthreads();

    float ss = 0.f;
    #pragma unroll
    for (int i = 0; i < 4; i++) {
        float d = row[tid + i * 256] - mu;
        ss += d * d;
    }
    red[tid] = ss; __syncthreads();
    #pragma unroll
    for (int off = 128; off > 0; off >>= 1) {
        if (tid < off) red[tid] += red[tid + off];
        __syncthreads();
    }
    const float inv = rsqrtf(red[0] * (1.f / DMOD) + 1e-5f);

    __half* yr = y + (long)r * DMOD;
    #pragma unroll
    for (int i = 0; i < 4; i++) {
        int c = tid + i * 256;
        yr[c] = __float2half_rn((row[c] - mu) * inv);
    }
}

// ---------------- fp16 GEMM 128x128: single pass, cp.async 2-stage --------------
#define GBK   32
#define PADK  40
#define GH_SMEM (2 * 2 * 128 * PADK * (int)sizeof(__half))   // 40960 B

__global__ void __launch_bounds__(256, 2) gemm_h(
    const __half* __restrict__ A, int lda,
    const __half* __restrict__ B, int ldb,
    float* __restrict__ C, int ldc, const float* __restrict__ Res, int K)
{
    extern __shared__ __half smh[];
    const int tid  = threadIdx.x;
    const int m0   = blockIdx.y * 128;
    const int n0   = blockIdx.x * 128;
    const int warp = tid >> 5;
    const int wm0  = (warp & 3) * 32;
    const int wn0  = (warp >> 2) * 64;

    wmma::fragment<wmma::accumulator, 16, 16, 16, float> acc[2][4];
    #pragma unroll
    for (int i = 0; i < 2; i++)
        #pragma unroll
        for (int j = 0; j < 4; j++) {
            if (Res) {
                const float* rp = Res + (long)(m0 + wm0 + 16 * i) * ldc
                                      + n0 + wn0 + 16 * j;
                wmma::load_matrix_sync(acc[i][j], rp, ldc, wmma::mem_row_major);
            } else {
                wmma::fill_fragment(acc[i][j], 0.f);
            }
        }

    const __half* Abase = A + (long)m0 * lda;
    const __half* Bbase = B + (long)n0 * ldb;

    #define GH_LOAD(ST, K0)                                                    \
    do {                                                                       \
        __half* sb = smh + (ST) * (2 * 128 * PADK);                            \
        _Pragma("unroll")                                                      \
        for (int t = 0; t < 4; t++) {                                          \
            int c   = tid + t * 256;                                           \
            int arr = c >> 9;                                                  \
            int rem = c & 511;                                                 \
            int row = rem >> 2;                                                \
            int col = (rem & 3) * 8;                                           \
            const __half* src = arr ? Bbase + (long)row * ldb + (K0) + col     \
                                    : Abase + (long)row * lda + (K0) + col;    \
            cp16h(sb + arr * (128 * PADK) + row * PADK + col, src);            \
        }                                                                      \
        asm volatile("cp.async.commit_group;\n" ::);                           \
    } while (0)

    const int nk = K / GBK;
    GH_LOAD(0, 0);

    for (int ks = 0; ks < nk; ks++) {
        asm volatile("cp.async.wait_group 0;\n" ::);
        __syncthreads();
        if (ks + 1 < nk) GH_LOAD((ks + 1) & 1, (ks + 1) * GBK);

        __half* sb = smh + (ks & 1) * (2 * 128 * PADK);
        __half* sA = sb;
        __half* sB = sb + 128 * PADK;

        #pragma unroll
        for (int k16 = 0; k16 < GBK; k16 += 16) {
            wmma::fragment<wmma::matrix_a, 16, 16, 16, __half, wmma::row_major> af[2];
            #pragma unroll
            for (int i = 0; i < 2; i++)
                wmma::load_matrix_sync(af[i], sA + (wm0 + 16 * i) * PADK + k16, PADK);
            #pragma unroll
            for (int j = 0; j < 4; j++) {
                wmma::fragment<wmma::matrix_b, 16, 16, 16, __half, wmma::col_major> bfr;
                wmma::load_matrix_sync(bfr, sB + (wn0 + 16 * j) * PADK + k16, PADK);
                #pragma unroll
                for (int i = 0; i < 2; i++)
                    wmma::mma_sync(acc[i][j], af[i], bfr, acc[i][j]);
            }
        }
    }

    #pragma unroll
    for (int i = 0; i < 2; i++)
        #pragma unroll
        for (int j = 0; j < 4; j++) {
            float* cp = C + (long)(m0 + wm0 + 16 * i) * ldc + n0 + wn0 + 16 * j;
            wmma::store_matrix_sync(cp, acc[i][j], ldc, wmma::mem_row_major);
        }
}

// ---------------- RoPE + head-major split: q,k bf16 hi/lo; v fp16 ---------------
__global__ void __launch_bounds__(256) rope_split(
    const float* __restrict__ qkv,
    bf16* __restrict__ qh, bf16* __restrict__ ql,
    bf16* __restrict__ kh, bf16* __restrict__ kl,
    __half* __restrict__ v16)
{
    const int idx = blockIdx.x * 256 + threadIdx.x;
    if (idx >= SEQ * NHEAD * 32) return;
    const int j = idx & 31;
    const int h = (idx >> 5) & (NHEAD - 1);
    const int l = idx >> 9;

    const float inv_freq = powf(10000.f, -(float)j / 32.f);
    const float ang = (float)l * inv_freq;
    float c, s;
    sincosf(ang, &s, &c);

    const float* qp = qkv + (long)l * (3 * DMOD) + h * HDIM + j;
    const float q1 = qp[0], q2 = qp[32];
    const float k1 = qp[DMOD], k2 = qp[DMOD + 32];
    const float v1 = qp[2 * DMOD], v2 = qp[2 * DMOD + 32];

    const long dst = ((long)h * SEQ + l) * HDIM + j;
    split_hl((q1 * c - q2 * s) * 0.125f, qh[dst],      ql[dst]);
    split_hl((q2 * c + q1 * s) * 0.125f, qh[dst + 32], ql[dst + 32]);
    split_hl(k1 * c - k2 * s,            kh[dst],      kl[dst]);
    split_hl(k2 * c + k1 * s,            kh[dst + 32], kl[dst + 32]);
    v16[dst]      = __float2half_rn(v1);
    v16[dst + 32] = __float2half_rn(v2);
}

// ---------------- Flash attention: 3-pass S, 1-pass fp16 PV, double-buffered ----
#define QSTR 80
#define FSTR 68
#define STG  (64 * QSTR)                 // elements per array per stage
// smem: sK[2 stages][hi/lo][STG] bf16 + sV[2][STG] half + Sf/Of fp32
#define AT3_SMEM (6 * STG * 2 + 2 * 64 * FSTR * 4)   // 96256 B

__global__ void __launch_bounds__(256, 2) attn3(
    const bf16* __restrict__ Qh, const bf16* __restrict__ Ql,
    const bf16* __restrict__ Kh, const bf16* __restrict__ Kl,
    const __half* __restrict__ V16,
    __half* __restrict__ out)
{
    extern __shared__ char smraw[];
    bf16*   sK = (bf16*)smraw;                       // [stage*2 + hi/lo][STG]
    __half* sV = (__half*)(smraw + 4 * STG * 2);     // [stage][STG]
    float*  Sf = (float*)(smraw + 6 * STG * 2);
    float*  Of = Sf + 64 * FSTR;

    const int h     = blockIdx.x;
    const int qb    = (int)gridDim.y - 1 - (int)blockIdx.y;
    const int tid   = threadIdx.x;
    const int warp  = tid >> 5;
    const int qbase = qb * 64;
    const int rt    = warp >> 1;
    const int chalf = (warp & 1) * 32;

    // ---- stage Q via stage-0 K buffers, read fragments once
    const long qoff = ((long)h * SEQ + qbase) * HDIM;
    #pragma unroll
    for (int t = 0; t < 2; t++) {
        int c = tid + t * 256;
        int row = c >> 3, ch = (c & 7) * 8;
        cp16b(sK + row * QSTR + ch,       Qh + qoff + row * HDIM + ch);
        cp16b(sK + STG + row * QSTR + ch, Ql + qoff + row * HDIM + ch);
    }
    asm volatile("cp.async.commit_group;\n" ::);
    asm volatile("cp.async.wait_group 0;\n" ::);
    __syncthreads();

    wmma::fragment<wmma::matrix_a, 16, 16, 16, bf16, wmma::row_major> qhf[4], qlf[4];
    #pragma unroll
    for (int ks = 0; ks < 4; ks++) {
        wmma::load_matrix_sync(qhf[ks], sK + rt * 16 * QSTR + ks * 16, QSTR);
        wmma::load_matrix_sync(qlf[ks], sK + STG + rt * 16 * QSTR + ks * 16, QSTR);
    }
    for (int i = tid; i < 64 * FSTR; i += 256) Of[i] = 0.f;
    __syncthreads();

    // ---- tile load macro (K hi/lo + V): 6 chunks/thread
    #define AT_LOAD(ST, KB)                                                     \
    do {                                                                        \
        const long koff = ((long)h * SEQ + (KB) * 64) * HDIM;                   \
        bf16*   dKh = sK + (ST) * 2 * STG;                                      \
        bf16*   dKl = dKh + STG;                                                \
        __half* dV  = sV + (ST) * STG;                                          \
        _Pragma("unroll")                                                       \
        for (int t = 0; t < 2; t++) {                                           \
            int c = tid + t * 256;                                              \
            int row = c >> 3, ch = (c & 7) * 8;                                 \
            cp16b(dKh + row * QSTR + ch, Kh  + koff + row * HDIM + ch);         \
            cp16b(dKl + row * QSTR + ch, Kl  + koff + row * HDIM + ch);         \
            cp16h(dV  + row * QSTR + ch, V16 + koff + row * HDIM + ch);         \
        }                                                                       \
        asm volatile("cp.async.commit_group;\n" ::);                            \
    } while (0)

    const int r  = tid >> 2;
    const int cs = (tid & 3) * 16;
    float mrow = -1e30f, lsum = 0.f, alpha = 0.f;

    AT_LOAD(0, 0);

    for (int kb = 0; kb <= qb; kb++) {
        const int st = kb & 1;
        asm volatile("cp.async.wait_group 0;\n" ::);
        __syncthreads();
        if (kb < qb) AT_LOAD(st ^ 1, kb + 1);   // overlap next load with compute

        bf16*   cKh = sK + st * 2 * STG;
        bf16*   cKl = cKh + STG;
        __half* cV  = sV + st * STG;
        __half* P   = (__half*)cKh;             // alias after S is computed

        // ---- S = Q K^T (3-pass bf16 split)
        #pragma unroll
        for (int ct = 0; ct < 2; ct++) {
            const int col0 = chalf + ct * 16;
            wmma::fragment<wmma::accumulator, 16, 16, 16, float> acc;
            wmma::fill_fragment(acc, 0.f);
            #pragma unroll
            for (int ks = 0; ks < 4; ks++) {
                wmma::fragment<wmma::matrix_b, 16, 16, 16, bf16, wmma::col_major> bh, bl;
                wmma::load_matrix_sync(bh, cKh + col0 * QSTR + ks * 16, QSTR);
                wmma::load_matrix_sync(bl, cKl + col0 * QSTR + ks * 16, QSTR);
                wmma::mma_sync(acc, qhf[ks], bl, acc);
                wmma::mma_sync(acc, qlf[ks], bh, acc);
                wmma::mma_sync(acc, qhf[ks], bh, acc);
            }
            wmma::store_matrix_sync(Sf + rt * 16 * FSTR + col0, acc, FSTR,
                                    wmma::mem_row_major);
        }
        __syncthreads();

        // ---- online softmax; write P (fp16, single)
        float s[16];
        #pragma unroll
        for (int j = 0; j < 16; j++) s[j] = Sf[r * FSTR + cs + j];
        if (kb == qb) {
            const int kbase = kb * 64;
            #pragma unroll
            for (int j = 0; j < 16; j++)
                if (kbase + cs + j > qbase + r) s[j] = -1e30f;
        }
        float mloc = s[0];
        #pragma unroll
        for (int j = 1; j < 16; j++) mloc = fmaxf(mloc, s[j]);
        mloc = fmaxf(mloc, __shfl_xor_sync(0xffffffffu, mloc, 1));
        mloc = fmaxf(mloc, __shfl_xor_sync(0xffffffffu, mloc, 2));
        const float mnew = fmaxf(mrow, mloc);
        alpha = __expf(mrow - mnew);

        float ps = 0.f;
        #pragma unroll
        for (int j = 0; j < 16; j++) {
            float p = __expf(s[j] - mnew);
            ps += p;
            P[r * QSTR + cs + j] = __float2half_rn(p);
        }
        ps += __shfl_xor_sync(0xffffffffu, ps, 1);
        ps += __shfl_xor_sync(0xffffffffu, ps, 2);
        lsum = lsum * alpha + ps;
        mrow = mnew;
        __syncthreads();

        // ---- T = P V (single-pass fp16) -> Sf
        #pragma unroll
        for (int ct = 0; ct < 2; ct++) {
            const int col0 = chalf + ct * 16;
            wmma::fragment<wmma::accumulator, 16, 16, 16, float> acc;
            wmma::fill_fragment(acc, 0.f);
            #pragma unroll
            for (int js = 0; js < 4; js++) {
                wmma::fragment<wmma::matrix_a, 16, 16, 16, __half, wmma::row_major> pf;
                wmma::load_matrix_sync(pf, P + rt * 16 * QSTR + js * 16, QSTR);
                wmma::fragment<wmma::matrix_b, 16, 16, 16, __half, wmma::row_major> vf;
                wmma::load_matrix_sync(vf, cV + js * 16 * QSTR + col0, QSTR);
                wmma::mma_sync(acc, pf, vf, acc);
            }
            wmma::store_matrix_sync(Sf + rt * 16 * FSTR + col0, acc, FSTR,
                                    wmma::mem_row_major);
        }
        __syncthreads();

        // ---- O = alpha*O + T   (thread-private cells; next sync orders reuse)
        #pragma unroll
        for (int j = 0; j < 16; j++) {
            int o = r * FSTR + cs + j;
            Of[o] = Of[o] * alpha + Sf[o];
        }
    }

    __syncthreads();
    const float invl = 1.f / lsum;
    __half* orow = out + (long)(qbase + r) * DMOD + h * HDIM + cs;
    #pragma unroll
    for (int j = 0; j < 16; j++)
        orow[j] = __float2half_rn(Of[r * FSTR + cs + j] * invl);
}

// ---------------- SwiGLU -> fp16 -------------------------------------------------
__global__ void __launch_bounds__(256) swiglu_kernel(const float* __restrict__ g,
                                                     __half* __restrict__ o) {
    const int idx = blockIdx.x * 256 + threadIdx.x;
    if (idx >= SEQ * (DMLP / 2)) return;
    const int rw = idx >> 12;
    const int c  = idx & 4095;
    const float x1 = g[(long)rw * DMLP + c];
    const float x2 = g[(long)rw * DMLP + (DMLP / 2) + c];
    const float sig = 1.f / (1.f + __expf(-x2));
    o[idx] = __float2half_rn(x2 * sig * x1);
}

// ---------------- launch ----------------------------------------------------------
extern "C" void kernel_launch(void* const* d_in, const int* in_sizes, int n_in,
                              void* d_out, int out_size) {
    const float* x      = (const float*)d_in[0];
    const float* W_attn = (const float*)d_in[2];
    const float* W_out  = (const float*)d_in[3];
    const float* W_ffp  = (const float*)d_in[4];
    const float* W_ffo  = (const float*)d_in[5];
    float* out = (float*)d_out;

    float *qkv, *h, *gbuf;
    __half *xn16, *at16, *hn16, *mlp16, *Wa16, *Wo16, *Wp16, *Wf16, *v16;
    bf16 *qh, *ql, *kh, *kl;
    cudaGetSymbolAddress((void**)&qkv,  g_qkv);
    cudaGetSymbolAddress((void**)&h,    g_h);
    cudaGetSymbolAddress((void**)&gbuf, g_g);
    cudaGetSymbolAddress((void**)&xn16, g_xn16);
    cudaGetSymbolAddress((void**)&at16, g_at16);
    cudaGetSymbolAddress((void**)&hn16, g_hn16);
    cudaGetSymbolAddress((void**)&mlp16,g_mlp16);
    cudaGetSymbolAddress((void**)&Wa16, g_Wa16);
    cudaGetSymbolAddress((void**)&Wo16, g_Wo16);
    cudaGetSymbolAddress((void**)&Wp16, g_Wp16);
    cudaGetSymbolAddress((void**)&Wf16, g_Wf16);
    cudaGetSymbolAddress((void**)&qh, g_qh); cudaGetSymbolAddress((void**)&ql, g_ql);
    cudaGetSymbolAddress((void**)&kh, g_kh); cudaGetSymbolAddress((void**)&kl, g_kl);
    cudaGetSymbolAddress((void**)&v16, g_v16);

    cudaFuncSetAttribute(attn3,
                         cudaFuncAttributeMaxDynamicSharedMemorySize, AT3_SMEM);
    cudaFuncSetAttribute(gemm_h,
                         cudaFuncAttributeMaxDynamicSharedMemorySize, GH_SMEM);

    // fused weight converts: 16M elements total
    {
        int n0 = 3 * DMOD * DMOD, n1 = DMOD * DMOD,
            n2 = DMLP * DMOD,     n3 = DMOD * DMLP / 2;
        long total = (long)n0 + n1 + n2 + n3;
        cvt_all<<<(int)(total / 8 / 256), 256>>>(W_attn, Wa16, n0, W_out, Wo16, n1,
                                                 W_ffp, Wp16, n2, W_ffo, Wf16, n3);
    }

    // 1) xn = LN(x) -> fp16
    ln_kernel<<<SEQ, 256>>>(x, xn16);

    // 2) qkv = xn @ W_attn^T
    gemm_h<<<dim3(3 * DMOD / 128, SEQ / 128), 256, GH_SMEM>>>(
        xn16, DMOD, Wa16, DMOD, qkv, 3 * DMOD, nullptr, DMOD);

    // 3) RoPE + head-major split
    rope_split<<<(SEQ * NHEAD * 32 + 255) / 256, 256>>>(qkv, qh, ql, kh, kl, v16);

    // 4) attention -> fp16
    attn3<<<dim3(NHEAD, SEQ / 64), 256, AT3_SMEM>>>(qh, ql, kh, kl, v16, at16);

    // 5) h = attn @ W_out^T + x
    gemm_h<<<dim3(DMOD / 128, SEQ / 128), 256, GH_SMEM>>>(
        at16, DMOD, Wo16, DMOD, h, DMOD, x, DMOD);

    // 6) hn = LN(h) -> fp16
    ln_kernel<<<SEQ, 256>>>(h, hn16);

    // 7) g = hn @ W_ffp^T
    gemm_h<<<dim3(DMLP / 128, SEQ / 128), 256, GH_SMEM>>>(
        hn16, DMOD, Wp16, DMOD, gbuf, DMLP, nullptr, DMOD);

    // 8) mlp = silu(g2)*g1 -> fp16
    swiglu_kernel<<<(SEQ * (DMLP / 2) + 255) / 256, 256>>>(gbuf, mlp16);

    // 9) out = mlp @ W_ffo^T + h
    gemm_h<<<dim3(DMOD / 128, SEQ / 128), 256, GH_SMEM>>>(
        mlp16, DMLP / 2, Wf16, DMLP / 2, out, DMOD, h, DMLP / 2);
}

// round 14
// speedup vs baseline: 2.7645x; 1.0116x over previous
#include <cuda_runtime.h>
#include <cuda_bf16.h>
#include <cuda_fp16.h>
#include <mma.h>
#include <math.h>
#include <cstdint>

using namespace nvcuda;
typedef __nv_bfloat16 bf16;

#define SEQ   2048
#define DMOD  1024
#define NHEAD 16
#define HDIM  64
#define DMLP  8192

// ---------------- scratch -----------------------------------------------------
__device__ float  g_qkv [SEQ * 3 * DMOD];
__device__ float  g_h   [SEQ * DMOD];
__device__ __half g_g16 [SEQ * DMLP];
__device__ __half g_xn16 [SEQ * DMOD];
__device__ __half g_at16 [SEQ * DMOD];
__device__ __half g_hn16 [SEQ * DMOD];
__device__ __half g_mlp16[SEQ * (DMLP / 2)];
__device__ __half g_Wa16[3 * DMOD * DMOD];
__device__ __half g_Wo16[DMOD * DMOD];
__device__ __half g_Wp16[DMLP * DMOD];
__device__ __half g_Wf16[DMOD * DMLP / 2];
// head-major RoPE'd q/k (bf16 hi/lo) and v (fp16):  [h][l][64]
__device__ bf16   g_qh[SEQ * DMOD], g_ql[SEQ * DMOD];
__device__ bf16   g_kh[SEQ * DMOD], g_kl[SEQ * DMOD];
__device__ __half g_v16[SEQ * DMOD];

__device__ __forceinline__ void split_hl(float v, bf16& h, bf16& l) {
    h = __float2bfloat16(v);
    l = __float2bfloat16(v - __bfloat162float(h));
}
__device__ __forceinline__ void cp16b(bf16* dst, const bf16* src) {
    uint32_t s = (uint32_t)__cvta_generic_to_shared(dst);
    asm volatile("cp.async.cg.shared.global [%0], [%1], 16;\n" :: "r"(s), "l"(src));
}
__device__ __forceinline__ void cp16h(__half* dst, const __half* src) {
    uint32_t s = (uint32_t)__cvta_generic_to_shared(dst);
    asm volatile("cp.async.cg.shared.global [%0], [%1], 16;\n" :: "r"(s), "l"(src));
}

// ---------------- fused fp32 -> fp16 convert for all 4 weights -----------------
__global__ void __launch_bounds__(256) cvt_all(
    const float* __restrict__ s0, __half* __restrict__ d0, int n0,
    const float* __restrict__ s1, __half* __restrict__ d1, int n1,
    const float* __restrict__ s2, __half* __restrict__ d2, int n2,
    const float* __restrict__ s3, __half* __restrict__ d3, int n3)
{
    long i = ((long)blockIdx.x * 256 + threadIdx.x) * 8;
    const float* s; __half* d; long off = i;
    if (off < n0)              { s = s0; d = d0; }
    else if ((off -= n0) < n1) { s = s1; d = d1; }
    else if ((off -= n1) < n2) { s = s2; d = d2; }
    else if ((off -= n2) < n3) { s = s3; d = d3; }
    else return;
    float4 v0 = *(const float4*)(s + off);
    float4 v1 = *(const float4*)(s + off + 4);
    float a[8] = {v0.x, v0.y, v0.z, v0.w, v1.x, v1.y, v1.z, v1.w};
    __align__(16) __half hh[8];
    #pragma unroll
    for (int e = 0; e < 8; e++) hh[e] = __float2half_rn(a[e]);
    *(uint4*)(d + off) = *(uint4*)hh;
}

// ---------------- LayerNorm -> fp16 ---------------------------------------------
__global__ void __launch_bounds__(256) ln_kernel(const float* __restrict__ x,
                                                 __half* __restrict__ y) {
    __shared__ float row[DMOD];
    __shared__ float red[256];
    const int r   = blockIdx.x;
    const int tid = threadIdx.x;
    const float* xr = x + (long)r * DMOD;

    float s = 0.f;
    #pragma unroll
    for (int i = 0; i < 4; i++) {
        float v = xr[tid + i * 256];
        row[tid + i * 256] = v;
        s += v;
    }
    red[tid] = s; __syncthreads();
    #pragma unroll
    for (int off = 128; off > 0; off >>= 1) {
        if (tid < off) red[tid] += red[tid + off];
        __syncthreads();
    }
    const float mu = red[0] * (1.f / DMOD);
    __syncthreads();

    float ss = 0.f;
    #pragma unroll
    for (int i = 0; i < 4; i++) {
        float d = row[tid + i * 256] - mu;
        ss += d * d;
    }
    red[tid] = ss; __syncthreads();
    #pragma unroll
    for (int off = 128; off > 0; off >>= 1) {
        if (tid < off) red[tid] += red[tid + off];
        __syncthreads();
    }
    const float inv = rsqrtf(red[0] * (1.f / DMOD) + 1e-5f);

    __half* yr = y + (long)r * DMOD;
    #pragma unroll
    for (int i = 0; i < 4; i++) {
        int c = tid + i * 256;
        yr[c] = __float2half_rn((row[c] - mu) * inv);
    }
}

// ---------------- fp16 GEMM 128x128 -> fp32 C (cp.async 2-stage) ----------------
#define GBK   32
#define PADK  40
#define GH_SMEM (2 * 2 * 128 * PADK * (int)sizeof(__half))   // 40960 B

#define GEMM_PROLOG_BODY                                                        \
    const int tid  = threadIdx.x;                                               \
    const int m0   = blockIdx.y * 128;                                          \
    const int n0   = blockIdx.x * 128;                                          \
    const int warp = tid >> 5;                                                  \
    const int wm0  = (warp & 3) * 32;                                           \
    const int wn0  = (warp >> 2) * 64;

#define GH_LOAD(ST, K0)                                                        \
do {                                                                           \
    __half* sb = smh + (ST) * (2 * 128 * PADK);                                \
    _Pragma("unroll")                                                          \
    for (int t = 0; t < 4; t++) {                                              \
        int c   = tid + t * 256;                                               \
        int arr = c >> 9;                                                      \
        int rem = c & 511;                                                     \
        int row = rem >> 2;                                                    \
        int col = (rem & 3) * 8;                                               \
        const __half* src = arr ? Bbase + (long)row * ldb + (K0) + col         \
                                : Abase + (long)row * lda + (K0) + col;        \
        cp16h(sb + arr * (128 * PADK) + row * PADK + col, src);                \
    }                                                                          \
    asm volatile("cp.async.commit_group;\n" ::);                               \
} while (0)

#define GEMM_MAINLOOP                                                           \
    const int nk = K / GBK;                                                     \
    GH_LOAD(0, 0);                                                              \
    for (int ks = 0; ks < nk; ks++) {                                           \
        asm volatile("cp.async.wait_group 0;\n" ::);                            \
        __syncthreads();                                                        \
        if (ks + 1 < nk) GH_LOAD((ks + 1) & 1, (ks + 1) * GBK);                 \
        __half* sb = smh + (ks & 1) * (2 * 128 * PADK);                         \
        __half* sA = sb;                                                        \
        __half* sB = sb + 128 * PADK;                                           \
        _Pragma("unroll")                                                       \
        for (int k16 = 0; k16 < GBK; k16 += 16) {                               \
            wmma::fragment<wmma::matrix_a, 16, 16, 16, __half,                  \
                           wmma::row_major> af[2];                              \
            _Pragma("unroll")                                                   \
            for (int i = 0; i < 2; i++)                                         \
                wmma::load_matrix_sync(af[i],                                   \
                    sA + (wm0 + 16 * i) * PADK + k16, PADK);                    \
            _Pragma("unroll")                                                   \
            for (int j = 0; j < 4; j++) {                                       \
                wmma::fragment<wmma::matrix_b, 16, 16, 16, __half,              \
                               wmma::col_major> bfr;                            \
                wmma::load_matrix_sync(bfr,                                     \
                    sB + (wn0 + 16 * j) * PADK + k16, PADK);                    \
                _Pragma("unroll")                                               \
                for (int i = 0; i < 2; i++)                                     \
                    wmma::mma_sync(acc[i][j], af[i], bfr, acc[i][j]);           \
            }                                                                   \
        }                                                                       \
    }

__global__ void __launch_bounds__(256, 2) gemm_h(
    const __half* __restrict__ A, int lda,
    const __half* __restrict__ B, int ldb,
    float* __restrict__ C, int ldc, const float* __restrict__ Res, int K)
{
    extern __shared__ __half smh[];
    GEMM_PROLOG_BODY
    wmma::fragment<wmma::accumulator, 16, 16, 16, float> acc[2][4];
    #pragma unroll
    for (int i = 0; i < 2; i++)
        #pragma unroll
        for (int j = 0; j < 4; j++) {
            if (Res) {
                const float* rp = Res + (long)(m0 + wm0 + 16 * i) * ldc
                                      + n0 + wn0 + 16 * j;
                wmma::load_matrix_sync(acc[i][j], rp, ldc, wmma::mem_row_major);
            } else {
                wmma::fill_fragment(acc[i][j], 0.f);
            }
        }
    const __half* Abase = A + (long)m0 * lda;
    const __half* Bbase = B + (long)n0 * ldb;
    GEMM_MAINLOOP
    #pragma unroll
    for (int i = 0; i < 2; i++)
        #pragma unroll
        for (int j = 0; j < 4; j++) {
            float* cp = C + (long)(m0 + wm0 + 16 * i) * ldc + n0 + wn0 + 16 * j;
            wmma::store_matrix_sync(cp, acc[i][j], ldc, wmma::mem_row_major);
        }
}

// ---------------- fp16 GEMM 128x128 -> fp16 C (smem-staged epilogue) ------------
#define CSTR 132
#define GH16_SMEM (128 * CSTR * (int)sizeof(float))   // 67584 B (> pipeline 40960)

__global__ void __launch_bounds__(256, 2) gemm_h16(
    const __half* __restrict__ A, int lda,
    const __half* __restrict__ B, int ldb,
    __half* __restrict__ C, int ldc, int K)
{
    extern __shared__ __half smh[];
    GEMM_PROLOG_BODY
    wmma::fragment<wmma::accumulator, 16, 16, 16, float> acc[2][4];
    #pragma unroll
    for (int i = 0; i < 2; i++)
        #pragma unroll
        for (int j = 0; j < 4; j++) wmma::fill_fragment(acc[i][j], 0.f);
    const __half* Abase = A + (long)m0 * lda;
    const __half* Bbase = B + (long)n0 * ldb;
    GEMM_MAINLOOP

    __syncthreads();                       // pipeline buffers dead; reuse as fp32 tile
    float* Ct = (float*)smh;
    #pragma unroll
    for (int i = 0; i < 2; i++)
        #pragma unroll
        for (int j = 0; j < 4; j++)
            wmma::store_matrix_sync(Ct + (wm0 + 16 * i) * CSTR + wn0 + 16 * j,
                                    acc[i][j], CSTR, wmma::mem_row_major);
    __syncthreads();
    // 128x128 floats -> fp16 global; 256 threads x 16 iters x 4 elems
    #pragma unroll
    for (int t = 0; t < 16; t++) {
        int c = (tid + t * 256) * 4;       // 0..65532
        int row = c >> 7, col = c & 127;
        float4 v = *(float4*)(Ct + row * CSTR + col);
        __align__(8) __half hh[4] = {__float2half_rn(v.x), __float2half_rn(v.y),
                                     __float2half_rn(v.z), __float2half_rn(v.w)};
        *(uint2*)(C + (long)(m0 + row) * ldc + n0 + col) = *(uint2*)hh;
    }
}

// ---------------- RoPE + head-major split: q,k bf16 hi/lo; v fp16 ---------------
__global__ void __launch_bounds__(256) rope_split(
    const float* __restrict__ qkv,
    bf16* __restrict__ qh, bf16* __restrict__ ql,
    bf16* __restrict__ kh, bf16* __restrict__ kl,
    __half* __restrict__ v16)
{
    const int idx = blockIdx.x * 256 + threadIdx.x;
    if (idx >= SEQ * NHEAD * 32) return;
    const int j = idx & 31;
    const int h = (idx >> 5) & (NHEAD - 1);
    const int l = idx >> 9;

    const float inv_freq = powf(10000.f, -(float)j / 32.f);
    const float ang = (float)l * inv_freq;
    float c, s;
    sincosf(ang, &s, &c);

    const float* qp = qkv + (long)l * (3 * DMOD) + h * HDIM + j;
    const float q1 = qp[0], q2 = qp[32];
    const float k1 = qp[DMOD], k2 = qp[DMOD + 32];
    const float v1 = qp[2 * DMOD], v2 = qp[2 * DMOD + 32];

    const long dst = ((long)h * SEQ + l) * HDIM + j;
    split_hl((q1 * c - q2 * s) * 0.125f, qh[dst],      ql[dst]);
    split_hl((q2 * c + q1 * s) * 0.125f, qh[dst + 32], ql[dst + 32]);
    split_hl(k1 * c - k2 * s,            kh[dst],      kl[dst]);
    split_hl(k2 * c + k1 * s,            kh[dst + 32], kl[dst + 32]);
    v16[dst]      = __float2half_rn(v1);
    v16[dst + 32] = __float2half_rn(v2);
}

// ---------------- Flash attention Q128: 3-pass S, 1-pass fp16 PV ----------------
// 512 threads, Q tile 128x64, K/V tiles 64x64 double-buffered.
#define QSTR 80
#define FSTR 68
#define STG  (64 * QSTR)
#define AT4_SMEM (6 * STG * 2 + 2 * 128 * FSTR * 4)   // 131072 B

__global__ void __launch_bounds__(512, 1) attn4(
    const bf16* __restrict__ Qh, const bf16* __restrict__ Ql,
    const bf16* __restrict__ Kh, const bf16* __restrict__ Kl,
    const __half* __restrict__ V16,
    __half* __restrict__ out)
{
    extern __shared__ char smraw[];
    bf16*   sK = (bf16*)smraw;                       // [stage*2 + hi/lo][STG]
    __half* sV = (__half*)(smraw + 4 * STG * 2);     // [stage][STG]
    float*  Sf = (float*)(smraw + 6 * STG * 2);
    float*  Of = Sf + 128 * FSTR;

    const int h     = blockIdx.x;
    const int qb    = (int)gridDim.y - 1 - (int)blockIdx.y;  // long rows first
    const int tid   = threadIdx.x;
    const int warp  = tid >> 5;                              // 0..15
    const int qbase = qb * 128;
    const int rt    = warp >> 1;                             // 0..7 row tile
    const int chalf = (warp & 1) * 32;

    // ---- stage Q (128 rows hi/lo) through the sK area (20480 elements)
    bf16* sQh = sK;
    bf16* sQl = sK + 128 * QSTR;
    const long qoff = ((long)h * SEQ + qbase) * HDIM;
    #pragma unroll
    for (int t = 0; t < 2; t++) {
        int c = tid + t * 512;             // 1024 chunks per array
        int row = c >> 3, ch = (c & 7) * 8;
        cp16b(sQh + row * QSTR + ch, Qh + qoff + row * HDIM + ch);
        cp16b(sQl + row * QSTR + ch, Ql + qoff + row * HDIM + ch);
    }
    asm volatile("cp.async.commit_group;\n" ::);
    asm volatile("cp.async.wait_group 0;\n" ::);
    __syncthreads();

    wmma::fragment<wmma::matrix_a, 16, 16, 16, bf16, wmma::row_major> qhf[4], qlf[4];
    #pragma unroll
    for (int ks = 0; ks < 4; ks++) {
        wmma::load_matrix_sync(qhf[ks], sQh + rt * 16 * QSTR + ks * 16, QSTR);
        wmma::load_matrix_sync(qlf[ks], sQl + rt * 16 * QSTR + ks * 16, QSTR);
    }
    for (int i = tid; i < 128 * FSTR; i += 512) Of[i] = 0.f;
    __syncthreads();

    // ---- tile load macro (Kh, Kl, V): 512 chunks each, 3/thread
    #define AT_LOAD(ST, KB)                                                     \
    do {                                                                        \
        const long koff = ((long)h * SEQ + (KB) * 64) * HDIM;                   \
        bf16*   dKh = sK + (ST) * 2 * STG;                                      \
        bf16*   dKl = dKh + STG;                                                \
        __half* dV  = sV + (ST) * STG;                                          \
        int c = tid;                                                            \
        int row = c >> 3, ch = (c & 7) * 8;                                     \
        cp16b(dKh + row * QSTR + ch, Kh  + koff + row * HDIM + ch);             \
        cp16b(dKl + row * QSTR + ch, Kl  + koff + row * HDIM + ch);             \
        cp16h(dV  + row * QSTR + ch, V16 + koff + row * HDIM + ch);             \
        asm volatile("cp.async.commit_group;\n" ::);                            \
    } while (0)

    const int r  = tid >> 2;               // 0..127
    const int cs = (tid & 3) * 16;
    float mrow = -1e30f, lsum = 0.f, alpha = 0.f;

    const int nkb = (qbase + 128) >> 6;     // K tiles covering causal span
    AT_LOAD(0, 0);

    for (int kb = 0; kb < nkb; kb++) {
        const int st = kb & 1;
        asm volatile("cp.async.wait_group 0;\n" ::);
        __syncthreads();
        if (kb + 1 < nkb) AT_LOAD(st ^ 1, kb + 1);

        bf16*   cKh = sK + st * 2 * STG;
        bf16*   cKl = cKh + STG;
        __half* cV  = sV + st * STG;
        __half* P   = (__half*)cKh;        // 128xQSTR fp16 over Kh+Kl (20480 B)

        // ---- S = Q K^T (3-pass bf16)
        #pragma unroll
        for (int ct = 0; ct < 2; ct++) {
            const int col0 = chalf + ct * 16;
            wmma::fragment<wmma::accumulator, 16, 16, 16, float> acc;
            wmma::fill_fragment(acc, 0.f);
            #pragma unroll
            for (int ks = 0; ks < 4; ks++) {
                wmma::fragment<wmma::matrix_b, 16, 16, 16, bf16, wmma::col_major> bh, bl;
                wmma::load_matrix_sync(bh, cKh + col0 * QSTR + ks * 16, QSTR);
                wmma::load_matrix_sync(bl, cKl + col0 * QSTR + ks * 16, QSTR);
                wmma::mma_sync(acc, qhf[ks], bl, acc);
                wmma::mma_sync(acc, qlf[ks], bh, acc);
                wmma::mma_sync(acc, qhf[ks], bh, acc);
            }
            wmma::store_matrix_sync(Sf + rt * 16 * FSTR + col0, acc, FSTR,
                                    wmma::mem_row_major);
        }
        __syncthreads();

        // ---- online softmax (4 threads per row)
        const int kbase = kb * 64;
        float s[16];
        #pragma unroll
        for (int j = 0; j < 16; j++) s[j] = Sf[r * FSTR + cs + j];
        if (kbase + 64 > qbase) {          // diagonal region
            #pragma unroll
            for (int j = 0; j < 16; j++)
                if (kbase + cs + j > qbase + r) s[j] = -1e30f;
        }
        float mloc = s[0];
        #pragma unroll
        for (int j = 1; j < 16; j++) mloc = fmaxf(mloc, s[j]);
        mloc = fmaxf(mloc, __shfl_xor_sync(0xffffffffu, mloc, 1));
        mloc = fmaxf(mloc, __shfl_xor_sync(0xffffffffu, mloc, 2));
        const float mnew = fmaxf(mrow, mloc);
        alpha = __expf(mrow - mnew);

        float ps = 0.f;
        #pragma unroll
        for (int j = 0; j < 16; j++) {
            float p = __expf(s[j] - mnew);
            ps += p;
            P[r * QSTR + cs + j] = __float2half_rn(p);
        }
        ps += __shfl_xor_sync(0xffffffffu, ps, 1);
        ps += __shfl_xor_sync(0xffffffffu, ps, 2);
        lsum = lsum * alpha + ps;
        mrow = mnew;
        __syncthreads();

        // ---- T = P V (single-pass fp16) -> Sf
        #pragma unroll
        for (int ct = 0; ct < 2; ct++) {
            const int col0 = chalf + ct * 16;
            wmma::fragment<wmma::accumulator, 16, 16, 16, float> acc;
            wmma::fill_fragment(acc, 0.f);
            #pragma unroll
            for (int js = 0; js < 4; js++) {
                wmma::fragment<wmma::matrix_a, 16, 16, 16, __half, wmma::row_major> pf;
                wmma::load_matrix_sync(pf, P + rt * 16 * QSTR + js * 16, QSTR);
                wmma::fragment<wmma::matrix_b, 16, 16, 16, __half, wmma::row_major> vf;
                wmma::load_matrix_sync(vf, cV + js * 16 * QSTR + col0, QSTR);
                wmma::mma_sync(acc, pf, vf, acc);
            }
            wmma::store_matrix_sync(Sf + rt * 16 * FSTR + col0, acc, FSTR,
                                    wmma::mem_row_major);
        }
        __syncthreads();

        #pragma unroll
        for (int j = 0; j < 16; j++) {
            int o = r * FSTR + cs + j;
            Of[o] = Of[o] * alpha + Sf[o];
        }
    }

    __syncthreads();
    const float invl = 1.f / lsum;
    __half* orow = out + (long)(qbase + r) * DMOD + h * HDIM + cs;
    #pragma unroll
    for (int j = 0; j < 16; j++)
        orow[j] = __float2half_rn(Of[r * FSTR + cs + j] * invl);
}

// ---------------- SwiGLU (fp16 in) -> fp16 ----------------------------------------
__global__ void __launch_bounds__(256) swiglu_kernel(const __half* __restrict__ g,
                                                     __half* __restrict__ o) {
    const int idx = blockIdx.x * 256 + threadIdx.x;
    if (idx >= SEQ * (DMLP / 2)) return;
    const int rw = idx >> 12;
    const int c  = idx & 4095;
    const float x1 = __half2float(g[(long)rw * DMLP + c]);
    const float x2 = __half2float(g[(long)rw * DMLP + (DMLP / 2) + c]);
    const float sig = 1.f / (1.f + __expf(-x2));
    o[idx] = __float2half_rn(x2 * sig * x1);
}

// ---------------- launch -----------------------------------------------------------
extern "C" void kernel_launch(void* const* d_in, const int* in_sizes, int n_in,
                              void* d_out, int out_size) {
    const float* x      = (const float*)d_in[0];
    const float* W_attn = (const float*)d_in[2];
    const float* W_out  = (const float*)d_in[3];
    const float* W_ffp  = (const float*)d_in[4];
    const float* W_ffo  = (const float*)d_in[5];
    float* out = (float*)d_out;

    float *qkv, *h;
    __half *g16, *xn16, *at16, *hn16, *mlp16, *Wa16, *Wo16, *Wp16, *Wf16, *v16;
    bf16 *qh, *ql, *kh, *kl;
    cudaGetSymbolAddress((void**)&qkv,  g_qkv);
    cudaGetSymbolAddress((void**)&h,    g_h);
    cudaGetSymbolAddress((void**)&g16,  g_g16);
    cudaGetSymbolAddress((void**)&xn16, g_xn16);
    cudaGetSymbolAddress((void**)&at16, g_at16);
    cudaGetSymbolAddress((void**)&hn16, g_hn16);
    cudaGetSymbolAddress((void**)&mlp16,g_mlp16);
    cudaGetSymbolAddress((void**)&Wa16, g_Wa16);
    cudaGetSymbolAddress((void**)&Wo16, g_Wo16);
    cudaGetSymbolAddress((void**)&Wp16, g_Wp16);
    cudaGetSymbolAddress((void**)&Wf16, g_Wf16);
    cudaGetSymbolAddress((void**)&qh, g_qh); cudaGetSymbolAddress((void**)&ql, g_ql);
    cudaGetSymbolAddress((void**)&kh, g_kh); cudaGetSymbolAddress((void**)&kl, g_kl);
    cudaGetSymbolAddress((void**)&v16, g_v16);

    cudaFuncSetAttribute(attn4,
                         cudaFuncAttributeMaxDynamicSharedMemorySize, AT4_SMEM);
    cudaFuncSetAttribute(gemm_h,
                         cudaFuncAttributeMaxDynamicSharedMemorySize, GH_SMEM);
    cudaFuncSetAttribute(gemm_h16,
                         cudaFuncAttributeMaxDynamicSharedMemorySize, GH16_SMEM);

    // fused weight converts
    {
        int n0 = 3 * DMOD * DMOD, n1 = DMOD * DMOD,
            n2 = DMLP * DMOD,     n3 = DMOD * DMLP / 2;
        long total = (long)n0 + n1 + n2 + n3;
        cvt_all<<<(int)(total / 8 / 256), 256>>>(W_attn, Wa16, n0, W_out, Wo16, n1,
                                                 W_ffp, Wp16, n2, W_ffo, Wf16, n3);
    }

    // 1) xn = LN(x) -> fp16
    ln_kernel<<<SEQ, 256>>>(x, xn16);

    // 2) qkv = xn @ W_attn^T  (fp32 out, feeds RoPE)
    gemm_h<<<dim3(3 * DMOD / 128, SEQ / 128), 256, GH_SMEM>>>(
        xn16, DMOD, Wa16, DMOD, qkv, 3 * DMOD, nullptr, DMOD);

    // 3) RoPE + head-major split
    rope_split<<<(SEQ * NHEAD * 32 + 255) / 256, 256>>>(qkv, qh, ql, kh, kl, v16);

    // 4) attention (Q128) -> fp16
    attn4<<<dim3(NHEAD, SEQ / 128), 512, AT4_SMEM>>>(qh, ql, kh, kl, v16, at16);

    // 5) h = attn @ W_out^T + x  (fp32 out, feeds LN + final residual)
    gemm_h<<<dim3(DMOD / 128, SEQ / 128), 256, GH_SMEM>>>(
        at16, DMOD, Wo16, DMOD, h, DMOD, x, DMOD);

    // 6) hn = LN(h) -> fp16
    ln_kernel<<<SEQ, 256>>>(h, hn16);

    // 7) g = hn @ W_ffp^T  (fp16 out)
    gemm_h16<<<dim3(DMLP / 128, SEQ / 128), 256, GH16_SMEM>>>(
        hn16, DMOD, Wp16, DMOD, g16, DMLP, DMOD);

    // 8) mlp = silu(g2)*g1 -> fp16
    swiglu_kernel<<<(SEQ * (DMLP / 2) + 255) / 256, 256>>>(g16, mlp16);

    // 9) out = mlp @ W_ffo^T + h  (fp32 out)
    gemm_h<<<dim3(DMOD / 128, SEQ / 128), 256, GH_SMEM>>>(
        mlp16, DMLP / 2, Wf16, DMLP / 2, out, DMOD, h, DMLP / 2);
}